// round 1
// baseline (speedup 1.0000x reference)
#include <cuda_runtime.h>
#include <math.h>

#define BATCH  2
#define CH     512
#define NTOK   4096
#define GROUPS 32
#define CPG    16          // CH / GROUPS
#define EPS    1e-6f

// ---------------- scratch (static device globals; no allocation) ----------------
__device__ float g_h [(size_t)BATCH * CH * NTOK];
__device__ float g_q [(size_t)BATCH * CH * NTOK];
__device__ float g_k [(size_t)BATCH * CH * NTOK];
__device__ float g_v [(size_t)BATCH * CH * NTOK];
__device__ float g_ao[(size_t)BATCH * CH * NTOK];
__device__ float g_s [(size_t)BATCH * NTOK * NTOK];   // 134 MB scores/attn

// ---------------- GroupNorm: one block per (batch, group) ----------------
__global__ void gn_kernel(const float* __restrict__ x,
                          const float* __restrict__ gamma,
                          const float* __restrict__ beta)
{
    const int bg = blockIdx.x;            // 0 .. BATCH*GROUPS-1
    const int b = bg / GROUPS, g = bg % GROUPS;
    const size_t base = ((size_t)b * CH + (size_t)g * CPG) * NTOK;
    const float* xp = x + base;
    float* hp = g_h + base;
    const int M = CPG * NTOK;             // 65536

    float s = 0.f, s2 = 0.f;
    for (int i = threadIdx.x * 4; i < M; i += blockDim.x * 4) {
        float4 v = *(const float4*)&xp[i];
        s  += v.x + v.y + v.z + v.w;
        s2 += v.x*v.x + v.y*v.y + v.z*v.z + v.w*v.w;
    }
    __shared__ float shs[8], shs2[8], shbc[2];
    #pragma unroll
    for (int o = 16; o; o >>= 1) {
        s  += __shfl_xor_sync(0xFFFFFFFFu, s,  o);
        s2 += __shfl_xor_sync(0xFFFFFFFFu, s2, o);
    }
    const int wid = threadIdx.x >> 5, lane = threadIdx.x & 31;
    if (!lane) { shs[wid] = s; shs2[wid] = s2; }
    __syncthreads();
    if (threadIdx.x == 0) {
        float ts = 0.f, ts2 = 0.f;
        #pragma unroll
        for (int i = 0; i < 8; i++) { ts += shs[i]; ts2 += shs2[i]; }
        const float mean = ts / (float)M;
        const float var  = ts2 / (float)M - mean * mean;
        shbc[0] = mean;
        shbc[1] = rsqrtf(var + EPS);
    }
    __syncthreads();
    const float mean = shbc[0], rstd = shbc[1];
    for (int i = threadIdx.x * 4; i < M; i += blockDim.x * 4) {
        const int c = g * CPG + (i >> 12);          // i / NTOK
        const float ga = gamma[c] * rstd;
        const float be = beta[c] - mean * ga;
        float4 v = *(const float4*)&xp[i];
        float4 o;
        o.x = v.x * ga + be; o.y = v.y * ga + be;
        o.z = v.z * ga + be; o.w = v.w * ga + be;
        *(float4*)&hp[i] = o;
    }
}

// ---------------- generic 128x128x16 SGEMM, 8x8 micro-tiles ----------------
// C[m,n] = scale * sum_k A(m,k)*B(k,n)  (+ bias[m]) (+ resid[m,n])
// A_KC:  A stored A[m*lda + k]  (k contiguous)  else A[k*lda + m]
// B_NC:  B stored B[k*ldb + n]  (n contiguous)  else B[n*ldb + k]
template<bool A_KC, bool B_NC>
__global__ __launch_bounds__(256)
void gemm_kernel(const float* __restrict__ A,  size_t sAb,
                 const float* __restrict__ Bm, size_t sBb,
                 float* __restrict__ Cm,       size_t sCb,
                 const float* __restrict__ bias,
                 const float* __restrict__ resid, size_t sRb,
                 int K, int lda, int ldb, int ldc, float scale)
{
    __shared__ float As[16][128];
    __shared__ float Bs[16][128];
    const int tid = threadIdx.x;
    const int bz  = blockIdx.z;
    A  += sAb * bz;
    Bm += sBb * bz;
    Cm += sCb * bz;
    if (resid) resid += sRb * bz;
    const int m0 = blockIdx.y * 128, n0 = blockIdx.x * 128;
    const int ty = tid >> 4, tx = tid & 15;

    float acc[8][8];
    #pragma unroll
    for (int j = 0; j < 8; j++)
        #pragma unroll
        for (int i = 0; i < 8; i++) acc[j][i] = 0.f;

    for (int k0 = 0; k0 < K; k0 += 16) {
        // ---- load A tile -> As[k][m]
        if (A_KC) {
            const int r = tid >> 2, kc = (tid & 3) << 2;
            #pragma unroll
            for (int rr = 0; rr < 128; rr += 64) {
                float4 v = *(const float4*)&A[(size_t)(m0 + r + rr) * lda + (k0 + kc)];
                As[kc + 0][r + rr] = v.x; As[kc + 1][r + rr] = v.y;
                As[kc + 2][r + rr] = v.z; As[kc + 3][r + rr] = v.w;
            }
        } else {
            const int kr = tid >> 5, cc = (tid & 31) << 2;
            #pragma unroll
            for (int kk = 0; kk < 16; kk += 8)
                *(float4*)&As[kr + kk][cc] =
                    *(const float4*)&A[(size_t)(k0 + kr + kk) * lda + (m0 + cc)];
        }
        // ---- load B tile -> Bs[k][n]
        if (B_NC) {
            const int kr = tid >> 5, cc = (tid & 31) << 2;
            #pragma unroll
            for (int kk = 0; kk < 16; kk += 8)
                *(float4*)&Bs[kr + kk][cc] =
                    *(const float4*)&Bm[(size_t)(k0 + kr + kk) * ldb + (n0 + cc)];
        } else {
            const int r = tid >> 2, kc = (tid & 3) << 2;
            #pragma unroll
            for (int rr = 0; rr < 128; rr += 64) {
                float4 v = *(const float4*)&Bm[(size_t)(n0 + r + rr) * ldb + (k0 + kc)];
                Bs[kc + 0][r + rr] = v.x; Bs[kc + 1][r + rr] = v.y;
                Bs[kc + 2][r + rr] = v.z; Bs[kc + 3][r + rr] = v.w;
            }
        }
        __syncthreads();

        #pragma unroll
        for (int k = 0; k < 16; k++) {
            float a[8], bb[8];
            *(float4*)&a[0]  = *(const float4*)&As[k][ty * 8];
            *(float4*)&a[4]  = *(const float4*)&As[k][ty * 8 + 4];
            *(float4*)&bb[0] = *(const float4*)&Bs[k][tx * 8];
            *(float4*)&bb[4] = *(const float4*)&Bs[k][tx * 8 + 4];
            #pragma unroll
            for (int j = 0; j < 8; j++)
                #pragma unroll
                for (int i = 0; i < 8; i++)
                    acc[j][i] = fmaf(a[j], bb[i], acc[j][i]);
        }
        __syncthreads();
    }

    #pragma unroll
    for (int j = 0; j < 8; j++) {
        const int m  = m0 + ty * 8 + j;
        const float bv = bias ? bias[m] : 0.f;
        #pragma unroll
        for (int i = 0; i < 8; i += 4) {
            const int n = n0 + tx * 8 + i;
            float4 o;
            o.x = acc[j][i + 0] * scale + bv;
            o.y = acc[j][i + 1] * scale + bv;
            o.z = acc[j][i + 2] * scale + bv;
            o.w = acc[j][i + 3] * scale + bv;
            if (resid) {
                float4 rv = *(const float4*)&resid[(size_t)m * ldc + n];
                o.x += rv.x; o.y += rv.y; o.z += rv.z; o.w += rv.w;
            }
            *(float4*)&Cm[(size_t)m * ldc + n] = o;
        }
    }
}

// ---------------- row softmax over 4096 keys, one block per row ----------------
__global__ void softmax_kernel()
{
    float* p = g_s + (size_t)blockIdx.x * NTOK;
    const int t = threadIdx.x;                 // 256 threads, 16 elems each
    float vals[16];
    float mx = -1e30f;
    #pragma unroll
    for (int i = 0; i < 16; i++) {
        vals[i] = p[t + (i << 8)];
        mx = fmaxf(mx, vals[i]);
    }
    __shared__ float sh[8];
    #pragma unroll
    for (int o = 16; o; o >>= 1) mx = fmaxf(mx, __shfl_xor_sync(0xFFFFFFFFu, mx, o));
    if (!(t & 31)) sh[t >> 5] = mx;
    __syncthreads();
    if (t < 32) {
        float v = (t < 8) ? sh[t] : -1e30f;
        #pragma unroll
        for (int o = 4; o; o >>= 1) v = fmaxf(v, __shfl_xor_sync(0xFFFFFFFFu, v, o));
        if (!t) sh[0] = v;
    }
    __syncthreads();
    mx = sh[0];
    __syncthreads();

    float sum = 0.f;
    #pragma unroll
    for (int i = 0; i < 16; i++) {
        vals[i] = __expf(vals[i] - mx);
        sum += vals[i];
    }
    #pragma unroll
    for (int o = 16; o; o >>= 1) sum += __shfl_xor_sync(0xFFFFFFFFu, sum, o);
    if (!(t & 31)) sh[t >> 5] = sum;
    __syncthreads();
    if (t < 32) {
        float v = (t < 8) ? sh[t] : 0.f;
        #pragma unroll
        for (int o = 4; o; o >>= 1) v += __shfl_xor_sync(0xFFFFFFFFu, v, o);
        if (!t) sh[0] = v;
    }
    __syncthreads();
    const float inv = 1.f / sh[0];
    #pragma unroll
    for (int i = 0; i < 16; i++) p[t + (i << 8)] = vals[i] * inv;
}

// ---------------- launcher ----------------
extern "C" void kernel_launch(void* const* d_in, const int* in_sizes, int n_in,
                              void* d_out, int out_size)
{
    const float* x     = (const float*)d_in[0];
    const float* gamma = (const float*)d_in[1];
    const float* beta  = (const float*)d_in[2];
    const float* wq    = (const float*)d_in[3];
    const float* bq    = (const float*)d_in[4];
    const float* wk    = (const float*)d_in[5];
    const float* bk    = (const float*)d_in[6];
    const float* wv    = (const float*)d_in[7];
    const float* bv    = (const float*)d_in[8];
    const float* wo    = (const float*)d_in[9];
    const float* bo    = (const float*)d_in[10];
    float* out = (float*)d_out;

    float *h, *q, *k, *v, *ao, *s;
    cudaGetSymbolAddress((void**)&h,  g_h);
    cudaGetSymbolAddress((void**)&q,  g_q);
    cudaGetSymbolAddress((void**)&k,  g_k);
    cudaGetSymbolAddress((void**)&v,  g_v);
    cudaGetSymbolAddress((void**)&ao, g_ao);
    cudaGetSymbolAddress((void**)&s,  g_s);

    const size_t sCN = (size_t)CH * NTOK;
    const size_t sNN = (size_t)NTOK * NTOK;
    const float attn_scale = 0.044194173824159216f;   // 512^-0.5

    // 1) GroupNorm -> g_h
    gn_kernel<<<BATCH * GROUPS, 256>>>(x, gamma, beta);

    // 2) Q/K/V = W * h + b    (M=CH, N=NTOK, K=CH)
    dim3 gProj(NTOK / 128, CH / 128, BATCH);
    gemm_kernel<true, true><<<gProj, 256>>>(wq, 0, h, sCN, q, sCN, bq,
                                            (const float*)nullptr, 0,
                                            CH, CH, NTOK, NTOK, 1.f);
    gemm_kernel<true, true><<<gProj, 256>>>(wk, 0, h, sCN, k, sCN, bk,
                                            (const float*)nullptr, 0,
                                            CH, CH, NTOK, NTOK, 1.f);
    gemm_kernel<true, true><<<gProj, 256>>>(wv, 0, h, sCN, v, sCN, bv,
                                            (const float*)nullptr, 0,
                                            CH, CH, NTOK, NTOK, 1.f);

    // 3) scores = scale * Q^T K   (M=NTOK, N=NTOK, K=CH)
    dim3 gScore(NTOK / 128, NTOK / 128, BATCH);
    gemm_kernel<false, true><<<gScore, 256>>>(q, sCN, k, sCN, s, sNN,
                                              (const float*)nullptr,
                                              (const float*)nullptr, 0,
                                              CH, NTOK, NTOK, NTOK, attn_scale);

    // 4) softmax over keys (rows of g_s)
    softmax_kernel<<<BATCH * NTOK, 256>>>();

    // 5) ao = V * attn^T   (M=CH, N=NTOK, K=NTOK)
    dim3 gAV(NTOK / 128, CH / 128, BATCH);
    gemm_kernel<true, false><<<gAV, 256>>>(v, sCN, s, sNN, ao, sCN,
                                           (const float*)nullptr,
                                           (const float*)nullptr, 0,
                                           NTOK, NTOK, NTOK, NTOK, 1.f);

    // 6) out = x + Wo * ao + bo
    gemm_kernel<true, true><<<gProj, 256>>>(wo, 0, ao, sCN, out, sCN, bo,
                                            x, sCN,
                                            CH, CH, NTOK, NTOK, 1.f);
}

// round 2
// speedup vs baseline: 1.9797x; 1.9797x over previous
#include <cuda_runtime.h>
#include <math.h>

#define BATCH  2
#define CH     512
#define NTOK   4096
#define GROUPS 32
#define CPG    16
#define EPS    1e-6f

// ---------------- scratch (static device globals; no allocation) ----------------
__device__ float g_h [(size_t)BATCH * CH * NTOK];
__device__ float g_q [(size_t)BATCH * CH * NTOK];
__device__ float g_k [(size_t)BATCH * CH * NTOK];
__device__ float g_v [(size_t)BATCH * CH * NTOK];
__device__ float g_ao[(size_t)BATCH * CH * NTOK];
__device__ float g_s [(size_t)BATCH * NTOK * NTOK];   // 134 MB scores/attn

// ---------------- GroupNorm: one block per (batch, group) ----------------
__global__ void gn_kernel(const float* __restrict__ x,
                          const float* __restrict__ gamma,
                          const float* __restrict__ beta)
{
    const int bg = blockIdx.x;
    const int b = bg / GROUPS, g = bg % GROUPS;
    const size_t base = ((size_t)b * CH + (size_t)g * CPG) * NTOK;
    const float* xp = x + base;
    float* hp = g_h + base;
    const int M = CPG * NTOK;

    float s = 0.f, s2 = 0.f;
    for (int i = threadIdx.x * 4; i < M; i += blockDim.x * 4) {
        float4 v = *(const float4*)&xp[i];
        s  += v.x + v.y + v.z + v.w;
        s2 += v.x*v.x + v.y*v.y + v.z*v.z + v.w*v.w;
    }
    __shared__ float shs[8], shs2[8], shbc[2];
    #pragma unroll
    for (int o = 16; o; o >>= 1) {
        s  += __shfl_xor_sync(0xFFFFFFFFu, s,  o);
        s2 += __shfl_xor_sync(0xFFFFFFFFu, s2, o);
    }
    const int wid = threadIdx.x >> 5, lane = threadIdx.x & 31;
    if (!lane) { shs[wid] = s; shs2[wid] = s2; }
    __syncthreads();
    if (threadIdx.x == 0) {
        float ts = 0.f, ts2 = 0.f;
        #pragma unroll
        for (int i = 0; i < 8; i++) { ts += shs[i]; ts2 += shs2[i]; }
        const float mean = ts / (float)M;
        const float var  = ts2 / (float)M - mean * mean;
        shbc[0] = mean;
        shbc[1] = rsqrtf(var + EPS);
    }
    __syncthreads();
    const float mean = shbc[0], rstd = shbc[1];
    for (int i = threadIdx.x * 4; i < M; i += blockDim.x * 4) {
        const int c = g * CPG + (i >> 12);
        const float ga = gamma[c] * rstd;
        const float be = beta[c] - mean * ga;
        float4 v = *(const float4*)&xp[i];
        float4 o;
        o.x = v.x * ga + be; o.y = v.y * ga + be;
        o.z = v.z * ga + be; o.w = v.w * ga + be;
        *(float4*)&hp[i] = o;
    }
}

// ---------------- tf32 tensor-core GEMM, 128x128x32 block tile ----------------
// C[m,n] = scale * sum_k A(m,k)*B(k,n)  (+ bias[m]) (+ resid[m,n])
// A_KC:  A stored A[m*lda + k]  (k contiguous)  else A[k*lda + m]
// B_NC:  B stored B[k*ldb + n]  (n contiguous)  else B[n*ldb + k]

#define BK   32
#define PITCH 136   // floats per smem row: 16B aligned, rotates banks by 8/row

__device__ __forceinline__ unsigned f2tf32(float f) {
    unsigned u;
    asm("cvt.rna.tf32.f32 %0, %1;" : "=r"(u) : "f"(f));
    return u;
}

template<bool A_KC, bool B_NC>
__global__ __launch_bounds__(256, 2)
void gemm_tc(const float* __restrict__ A,  size_t sAb,
             const float* __restrict__ Bm, size_t sBb,
             float* __restrict__ Cm,       size_t sCb,
             const float* __restrict__ bias,
             const float* __restrict__ resid, size_t sRb,
             int K, int lda, int ldb, int ldc, float scale)
{
    __shared__ float As[BK][PITCH];
    __shared__ float Bs[BK][PITCH];

    const int tid = threadIdx.x;
    const int bz  = blockIdx.z;
    A  += sAb * bz;
    Bm += sBb * bz;
    Cm += sCb * bz;
    if (resid) resid += sRb * bz;
    const int m0 = blockIdx.y * 128, n0 = blockIdx.x * 128;

    const int warp = tid >> 5, lane = tid & 31;
    const int wm = (warp >> 2) * 64;    // 0 or 64
    const int wn = (warp & 3) * 32;     // 0,32,64,96
    const int grp = lane >> 2;          // 0..7
    const int tig = lane & 3;           // 0..3

    float acc[4][4][4];
    #pragma unroll
    for (int a = 0; a < 4; a++)
        #pragma unroll
        for (int b = 0; b < 4; b++)
            #pragma unroll
            for (int c = 0; c < 4; c++) acc[a][b][c] = 0.f;

    for (int k0 = 0; k0 < K; k0 += BK) {
        // ---- stage A tile -> As[k][m]
        if (A_KC) {
            const int kq = (tid & 7) << 2;   // k offset 0..28
            const int r  = tid >> 3;         // 0..31
            #pragma unroll
            for (int mm = 0; mm < 128; mm += 32) {
                float4 v = *(const float4*)&A[(size_t)(m0 + r + mm) * lda + (k0 + kq)];
                As[kq + 0][r + mm] = v.x; As[kq + 1][r + mm] = v.y;
                As[kq + 2][r + mm] = v.z; As[kq + 3][r + mm] = v.w;
            }
        } else {
            const int kr = tid >> 5;         // 0..7
            const int mc = (tid & 31) << 2;
            #pragma unroll
            for (int kk = 0; kk < BK; kk += 8)
                *(float4*)&As[kr + kk][mc] =
                    *(const float4*)&A[(size_t)(k0 + kr + kk) * lda + (m0 + mc)];
        }
        // ---- stage B tile -> Bs[k][n]
        if (B_NC) {
            const int kr = tid >> 5;
            const int nc = (tid & 31) << 2;
            #pragma unroll
            for (int kk = 0; kk < BK; kk += 8)
                *(float4*)&Bs[kr + kk][nc] =
                    *(const float4*)&Bm[(size_t)(k0 + kr + kk) * ldb + (n0 + nc)];
        } else {
            const int kq = (tid & 7) << 2;
            const int r  = tid >> 3;
            #pragma unroll
            for (int nn = 0; nn < 128; nn += 32) {
                float4 v = *(const float4*)&Bm[(size_t)(n0 + r + nn) * ldb + (k0 + kq)];
                Bs[kq + 0][r + nn] = v.x; Bs[kq + 1][r + nn] = v.y;
                Bs[kq + 2][r + nn] = v.z; Bs[kq + 3][r + nn] = v.w;
            }
        }
        __syncthreads();

        #pragma unroll
        for (int kc = 0; kc < BK; kc += 8) {
            unsigned af[4][4], bf[4][2];
            #pragma unroll
            for (int mi = 0; mi < 4; mi++) {
                const int m = wm + mi * 16 + grp;
                af[mi][0] = f2tf32(As[kc + tig    ][m    ]);
                af[mi][1] = f2tf32(As[kc + tig    ][m + 8]);
                af[mi][2] = f2tf32(As[kc + tig + 4][m    ]);
                af[mi][3] = f2tf32(As[kc + tig + 4][m + 8]);
            }
            #pragma unroll
            for (int nj = 0; nj < 4; nj++) {
                const int n = wn + nj * 8 + grp;
                bf[nj][0] = f2tf32(Bs[kc + tig    ][n]);
                bf[nj][1] = f2tf32(Bs[kc + tig + 4][n]);
            }
            #pragma unroll
            for (int mi = 0; mi < 4; mi++)
                #pragma unroll
                for (int nj = 0; nj < 4; nj++) {
                    asm volatile(
                        "mma.sync.aligned.m16n8k8.row.col.f32.tf32.tf32.f32 "
                        "{%0,%1,%2,%3}, {%4,%5,%6,%7}, {%8,%9}, {%0,%1,%2,%3};"
                        : "+f"(acc[mi][nj][0]), "+f"(acc[mi][nj][1]),
                          "+f"(acc[mi][nj][2]), "+f"(acc[mi][nj][3])
                        : "r"(af[mi][0]), "r"(af[mi][1]),
                          "r"(af[mi][2]), "r"(af[mi][3]),
                          "r"(bf[nj][0]), "r"(bf[nj][1]));
                }
        }
        __syncthreads();
    }

    // ---- epilogue
    #pragma unroll
    for (int mi = 0; mi < 4; mi++) {
        const int mA = m0 + wm + mi * 16 + grp;
        const int mB = mA + 8;
        const float bvA = bias ? bias[mA] : 0.f;
        const float bvB = bias ? bias[mB] : 0.f;
        #pragma unroll
        for (int nj = 0; nj < 4; nj++) {
            const int n = n0 + wn + nj * 8 + (tig << 1);
            float2 o0, o1;
            o0.x = acc[mi][nj][0] * scale + bvA;
            o0.y = acc[mi][nj][1] * scale + bvA;
            o1.x = acc[mi][nj][2] * scale + bvB;
            o1.y = acc[mi][nj][3] * scale + bvB;
            if (resid) {
                float2 r0 = *(const float2*)&resid[(size_t)mA * ldc + n];
                float2 r1 = *(const float2*)&resid[(size_t)mB * ldc + n];
                o0.x += r0.x; o0.y += r0.y;
                o1.x += r1.x; o1.y += r1.y;
            }
            *(float2*)&Cm[(size_t)mA * ldc + n] = o0;
            *(float2*)&Cm[(size_t)mB * ldc + n] = o1;
        }
    }
}

// ---------------- row softmax over 4096 keys ----------------
__global__ void softmax_kernel()
{
    float* p = g_s + (size_t)blockIdx.x * NTOK;
    const int t = threadIdx.x;
    float vals[16];
    float mx = -1e30f;
    #pragma unroll
    for (int i = 0; i < 16; i++) {
        vals[i] = p[t + (i << 8)];
        mx = fmaxf(mx, vals[i]);
    }
    __shared__ float sh[8];
    #pragma unroll
    for (int o = 16; o; o >>= 1) mx = fmaxf(mx, __shfl_xor_sync(0xFFFFFFFFu, mx, o));
    if (!(t & 31)) sh[t >> 5] = mx;
    __syncthreads();
    if (t < 32) {
        float v = (t < 8) ? sh[t] : -1e30f;
        #pragma unroll
        for (int o = 4; o; o >>= 1) v = fmaxf(v, __shfl_xor_sync(0xFFFFFFFFu, v, o));
        if (!t) sh[0] = v;
    }
    __syncthreads();
    mx = sh[0];
    __syncthreads();

    float sum = 0.f;
    #pragma unroll
    for (int i = 0; i < 16; i++) {
        vals[i] = __expf(vals[i] - mx);
        sum += vals[i];
    }
    #pragma unroll
    for (int o = 16; o; o >>= 1) sum += __shfl_xor_sync(0xFFFFFFFFu, sum, o);
    if (!(t & 31)) sh[t >> 5] = sum;
    __syncthreads();
    if (t < 32) {
        float v = (t < 8) ? sh[t] : 0.f;
        #pragma unroll
        for (int o = 4; o; o >>= 1) v += __shfl_xor_sync(0xFFFFFFFFu, v, o);
        if (!t) sh[0] = v;
    }
    __syncthreads();
    const float inv = 1.f / sh[0];
    #pragma unroll
    for (int i = 0; i < 16; i++) p[t + (i << 8)] = vals[i] * inv;
}

// ---------------- launcher ----------------
extern "C" void kernel_launch(void* const* d_in, const int* in_sizes, int n_in,
                              void* d_out, int out_size)
{
    const float* x     = (const float*)d_in[0];
    const float* gamma = (const float*)d_in[1];
    const float* beta  = (const float*)d_in[2];
    const float* wq    = (const float*)d_in[3];
    const float* bq    = (const float*)d_in[4];
    const float* wk    = (const float*)d_in[5];
    const float* bk    = (const float*)d_in[6];
    const float* wv    = (const float*)d_in[7];
    const float* bv    = (const float*)d_in[8];
    const float* wo    = (const float*)d_in[9];
    const float* bo    = (const float*)d_in[10];
    float* out = (float*)d_out;

    float *h, *q, *k, *v, *ao, *s;
    cudaGetSymbolAddress((void**)&h,  g_h);
    cudaGetSymbolAddress((void**)&q,  g_q);
    cudaGetSymbolAddress((void**)&k,  g_k);
    cudaGetSymbolAddress((void**)&v,  g_v);
    cudaGetSymbolAddress((void**)&ao, g_ao);
    cudaGetSymbolAddress((void**)&s,  g_s);

    const size_t sCN = (size_t)CH * NTOK;
    const size_t sNN = (size_t)NTOK * NTOK;
    const float attn_scale = 0.044194173824159216f;   // 512^-0.5

    // 1) GroupNorm -> g_h
    gn_kernel<<<BATCH * GROUPS, 256>>>(x, gamma, beta);

    // 2) Q/K/V = W * h + b    (M=CH, N=NTOK, K=CH)
    dim3 gProj(NTOK / 128, CH / 128, BATCH);
    gemm_tc<true, true><<<gProj, 256>>>(wq, 0, h, sCN, q, sCN, bq,
                                        (const float*)nullptr, 0,
                                        CH, CH, NTOK, NTOK, 1.f);
    gemm_tc<true, true><<<gProj, 256>>>(wk, 0, h, sCN, k, sCN, bk,
                                        (const float*)nullptr, 0,
                                        CH, CH, NTOK, NTOK, 1.f);
    gemm_tc<true, true><<<gProj, 256>>>(wv, 0, h, sCN, v, sCN, bv,
                                        (const float*)nullptr, 0,
                                        CH, CH, NTOK, NTOK, 1.f);

    // 3) scores = scale * Q^T K   (M=NTOK, N=NTOK, K=CH)
    dim3 gScore(NTOK / 128, NTOK / 128, BATCH);
    gemm_tc<false, true><<<gScore, 256>>>(q, sCN, k, sCN, s, sNN,
                                          (const float*)nullptr,
                                          (const float*)nullptr, 0,
                                          CH, NTOK, NTOK, NTOK, attn_scale);

    // 4) softmax over keys (rows of g_s)
    softmax_kernel<<<BATCH * NTOK, 256>>>();

    // 5) ao = V * attn^T   (M=CH, N=NTOK, K=NTOK)
    dim3 gAV(NTOK / 128, CH / 128, BATCH);
    gemm_tc<true, false><<<gAV, 256>>>(v, sCN, s, sNN, ao, sCN,
                                       (const float*)nullptr,
                                       (const float*)nullptr, 0,
                                       NTOK, NTOK, NTOK, NTOK, 1.f);

    // 6) out = x + Wo * ao + bo
    gemm_tc<true, true><<<gProj, 256>>>(wo, 0, ao, sCN, out, sCN, bo,
                                        x, sCN,
                                        CH, CH, NTOK, NTOK, 1.f);
}

// round 3
// speedup vs baseline: 2.5858x; 1.3062x over previous
#include <cuda_runtime.h>
#include <math.h>

#define BATCH  2
#define CH     512
#define NTOK   4096
#define GROUPS 32
#define CPG    16
#define EPS    1e-6f

// ---------------- scratch (static device globals; no allocation) ----------------
__device__ float g_h [(size_t)BATCH * CH * NTOK];
__device__ float g_q [(size_t)BATCH * CH * NTOK];
__device__ float g_k [(size_t)BATCH * CH * NTOK];
__device__ float g_v [(size_t)BATCH * CH * NTOK];
__device__ float g_ao[(size_t)BATCH * CH * NTOK];
__device__ float g_s [(size_t)BATCH * NTOK * NTOK];   // 134 MB scores/attn

// ---------------- GroupNorm ----------------
__global__ void gn_kernel(const float* __restrict__ x,
                          const float* __restrict__ gamma,
                          const float* __restrict__ beta)
{
    const int bg = blockIdx.x;
    const int b = bg / GROUPS, g = bg % GROUPS;
    const size_t base = ((size_t)b * CH + (size_t)g * CPG) * NTOK;
    const float* xp = x + base;
    float* hp = g_h + base;
    const int M = CPG * NTOK;

    float s = 0.f, s2 = 0.f;
    for (int i = threadIdx.x * 4; i < M; i += blockDim.x * 4) {
        float4 v = *(const float4*)&xp[i];
        s  += v.x + v.y + v.z + v.w;
        s2 += v.x*v.x + v.y*v.y + v.z*v.z + v.w*v.w;
    }
    __shared__ float shs[8], shs2[8], shbc[2];
    #pragma unroll
    for (int o = 16; o; o >>= 1) {
        s  += __shfl_xor_sync(0xFFFFFFFFu, s,  o);
        s2 += __shfl_xor_sync(0xFFFFFFFFu, s2, o);
    }
    const int wid = threadIdx.x >> 5, lane = threadIdx.x & 31;
    if (!lane) { shs[wid] = s; shs2[wid] = s2; }
    __syncthreads();
    if (threadIdx.x == 0) {
        float ts = 0.f, ts2 = 0.f;
        #pragma unroll
        for (int i = 0; i < 8; i++) { ts += shs[i]; ts2 += shs2[i]; }
        const float mean = ts / (float)M;
        const float var  = ts2 / (float)M - mean * mean;
        shbc[0] = mean;
        shbc[1] = rsqrtf(var + EPS);
    }
    __syncthreads();
    const float mean = shbc[0], rstd = shbc[1];
    for (int i = threadIdx.x * 4; i < M; i += blockDim.x * 4) {
        const int c = g * CPG + (i >> 12);
        const float ga = gamma[c] * rstd;
        const float be = beta[c] - mean * ga;
        float4 v = *(const float4*)&xp[i];
        float4 o;
        o.x = v.x * ga + be; o.y = v.y * ga + be;
        o.z = v.z * ga + be; o.w = v.w * ga + be;
        *(float4*)&hp[i] = o;
    }
}

// ---------------- tf32 tensor-core GEMM core ----------------
// C[m,n] = scale * sum_k A(m,k)*B(k,n)  (+ bias[m]) (+ resid[m,n])
// A_KC:  A stored A[m*lda + k]  else A[k*lda + m]
// B_NC:  B stored B[k*ldb + n]  else B[n*ldb + k]
// BK=16, double-buffered smem with register prefetch; smem holds tf32 bits.

#define BK    16
#define PITCH 136

__device__ __forceinline__ unsigned f2tf32(float f) {
    unsigned u;
    asm("cvt.rna.tf32.f32 %0, %1;" : "=r"(u) : "f"(f));
    return u;
}

template<bool A_KC, bool B_NC>
__device__ __forceinline__
void gemm_body(const float* __restrict__ A,
               const float* __restrict__ Bm,
               float* __restrict__ Cm,
               const float* __restrict__ bias,
               const float* __restrict__ resid,
               int K, int lda, int ldb, int ldc, float scale,
               int m0, int n0)
{
    __shared__ unsigned As[2][BK][PITCH];
    __shared__ unsigned Bs[2][BK][PITCH];

    const int tid = threadIdx.x;
    const int warp = tid >> 5, lane = tid & 31;
    const int wm = (warp >> 2) * 64;
    const int wn = (warp & 3) * 32;
    const int grp = lane >> 2;
    const int tig = lane & 3;

    // staging index precompute
    const int r  = tid >> 2;          // 0..63  (KC-style loads)
    const int kq = (tid & 3) << 2;    // 0,4,8,12
    const int kr = tid >> 5;          // 0..7   (MC/NC-style loads)
    const int mc = (tid & 31) << 2;

    float acc[4][4][4];
    #pragma unroll
    for (int a = 0; a < 4; a++)
        #pragma unroll
        for (int b = 0; b < 4; b++)
            #pragma unroll
            for (int c = 0; c < 4; c++) acc[a][b][c] = 0.f;

    float4 ra0, ra1, rb0, rb1;

    // ---- prologue: load k-slab 0
    if (A_KC) {
        ra0 = *(const float4*)&A[(size_t)(m0 + r)      * lda + kq];
        ra1 = *(const float4*)&A[(size_t)(m0 + r + 64) * lda + kq];
    } else {
        ra0 = *(const float4*)&A[(size_t)(kr)     * lda + m0 + mc];
        ra1 = *(const float4*)&A[(size_t)(kr + 8) * lda + m0 + mc];
    }
    if (B_NC) {
        rb0 = *(const float4*)&Bm[(size_t)(kr)     * ldb + n0 + mc];
        rb1 = *(const float4*)&Bm[(size_t)(kr + 8) * ldb + n0 + mc];
    } else {
        rb0 = *(const float4*)&Bm[(size_t)(n0 + r)      * ldb + kq];
        rb1 = *(const float4*)&Bm[(size_t)(n0 + r + 64) * ldb + kq];
    }

    auto store_tiles = [&](int buf) {
        if (A_KC) {
            As[buf][kq + 0][r] = f2tf32(ra0.x); As[buf][kq + 1][r] = f2tf32(ra0.y);
            As[buf][kq + 2][r] = f2tf32(ra0.z); As[buf][kq + 3][r] = f2tf32(ra0.w);
            As[buf][kq + 0][r + 64] = f2tf32(ra1.x); As[buf][kq + 1][r + 64] = f2tf32(ra1.y);
            As[buf][kq + 2][r + 64] = f2tf32(ra1.z); As[buf][kq + 3][r + 64] = f2tf32(ra1.w);
        } else {
            uint4 u0 = make_uint4(f2tf32(ra0.x), f2tf32(ra0.y), f2tf32(ra0.z), f2tf32(ra0.w));
            uint4 u1 = make_uint4(f2tf32(ra1.x), f2tf32(ra1.y), f2tf32(ra1.z), f2tf32(ra1.w));
            *(uint4*)&As[buf][kr][mc]     = u0;
            *(uint4*)&As[buf][kr + 8][mc] = u1;
        }
        if (B_NC) {
            uint4 u0 = make_uint4(f2tf32(rb0.x), f2tf32(rb0.y), f2tf32(rb0.z), f2tf32(rb0.w));
            uint4 u1 = make_uint4(f2tf32(rb1.x), f2tf32(rb1.y), f2tf32(rb1.z), f2tf32(rb1.w));
            *(uint4*)&Bs[buf][kr][mc]     = u0;
            *(uint4*)&Bs[buf][kr + 8][mc] = u1;
        } else {
            Bs[buf][kq + 0][r] = f2tf32(rb0.x); Bs[buf][kq + 1][r] = f2tf32(rb0.y);
            Bs[buf][kq + 2][r] = f2tf32(rb0.z); Bs[buf][kq + 3][r] = f2tf32(rb0.w);
            Bs[buf][kq + 0][r + 64] = f2tf32(rb1.x); Bs[buf][kq + 1][r + 64] = f2tf32(rb1.y);
            Bs[buf][kq + 2][r + 64] = f2tf32(rb1.z); Bs[buf][kq + 3][r + 64] = f2tf32(rb1.w);
        }
    };

    store_tiles(0);
    __syncthreads();

    int buf = 0;
    for (int k0 = 0; k0 < K; k0 += BK, buf ^= 1) {
        const bool has_next = (k0 + BK) < K;
        if (has_next) {
            const int kn = k0 + BK;
            if (A_KC) {
                ra0 = *(const float4*)&A[(size_t)(m0 + r)      * lda + kn + kq];
                ra1 = *(const float4*)&A[(size_t)(m0 + r + 64) * lda + kn + kq];
            } else {
                ra0 = *(const float4*)&A[(size_t)(kn + kr)     * lda + m0 + mc];
                ra1 = *(const float4*)&A[(size_t)(kn + kr + 8) * lda + m0 + mc];
            }
            if (B_NC) {
                rb0 = *(const float4*)&Bm[(size_t)(kn + kr)     * ldb + n0 + mc];
                rb1 = *(const float4*)&Bm[(size_t)(kn + kr + 8) * ldb + n0 + mc];
            } else {
                rb0 = *(const float4*)&Bm[(size_t)(n0 + r)      * ldb + kn + kq];
                rb1 = *(const float4*)&Bm[(size_t)(n0 + r + 64) * ldb + kn + kq];
            }
        }

        #pragma unroll
        for (int kc = 0; kc < BK; kc += 8) {
            unsigned af[4][4], bf[4][2];
            #pragma unroll
            for (int mi = 0; mi < 4; mi++) {
                const int m = wm + mi * 16 + grp;
                af[mi][0] = As[buf][kc + tig    ][m    ];
                af[mi][1] = As[buf][kc + tig    ][m + 8];
                af[mi][2] = As[buf][kc + tig + 4][m    ];
                af[mi][3] = As[buf][kc + tig + 4][m + 8];
            }
            #pragma unroll
            for (int nj = 0; nj < 4; nj++) {
                const int n = wn + nj * 8 + grp;
                bf[nj][0] = Bs[buf][kc + tig    ][n];
                bf[nj][1] = Bs[buf][kc + tig + 4][n];
            }
            #pragma unroll
            for (int mi = 0; mi < 4; mi++)
                #pragma unroll
                for (int nj = 0; nj < 4; nj++) {
                    asm volatile(
                        "mma.sync.aligned.m16n8k8.row.col.f32.tf32.tf32.f32 "
                        "{%0,%1,%2,%3}, {%4,%5,%6,%7}, {%8,%9}, {%0,%1,%2,%3};"
                        : "+f"(acc[mi][nj][0]), "+f"(acc[mi][nj][1]),
                          "+f"(acc[mi][nj][2]), "+f"(acc[mi][nj][3])
                        : "r"(af[mi][0]), "r"(af[mi][1]),
                          "r"(af[mi][2]), "r"(af[mi][3]),
                          "r"(bf[nj][0]), "r"(bf[nj][1]));
                }
        }

        if (has_next) {
            store_tiles(buf ^ 1);
            __syncthreads();
        }
    }

    // ---- epilogue
    #pragma unroll
    for (int mi = 0; mi < 4; mi++) {
        const int mA = m0 + wm + mi * 16 + grp;
        const int mB = mA + 8;
        const float bvA = bias ? bias[mA] : 0.f;
        const float bvB = bias ? bias[mB] : 0.f;
        #pragma unroll
        for (int nj = 0; nj < 4; nj++) {
            const int n = n0 + wn + nj * 8 + (tig << 1);
            float2 o0, o1;
            o0.x = acc[mi][nj][0] * scale + bvA;
            o0.y = acc[mi][nj][1] * scale + bvA;
            o1.x = acc[mi][nj][2] * scale + bvB;
            o1.y = acc[mi][nj][3] * scale + bvB;
            if (resid) {
                float2 r0 = *(const float2*)&resid[(size_t)mA * ldc + n];
                float2 r1 = *(const float2*)&resid[(size_t)mB * ldc + n];
                o0.x += r0.x; o0.y += r0.y;
                o1.x += r1.x; o1.y += r1.y;
            }
            *(float2*)&Cm[(size_t)mA * ldc + n] = o0;
            *(float2*)&Cm[(size_t)mB * ldc + n] = o1;
        }
    }
}

// generic wrapper (z = batch)
template<bool A_KC, bool B_NC>
__global__ __launch_bounds__(256, 2)
void gemm_tc(const float* __restrict__ A,  size_t sAb,
             const float* __restrict__ Bm, size_t sBb,
             float* __restrict__ Cm,       size_t sCb,
             const float* __restrict__ bias,
             const float* __restrict__ resid, size_t sRb,
             int K, int lda, int ldb, int ldc, float scale)
{
    const int bz = blockIdx.z;
    gemm_body<A_KC, B_NC>(A + sAb * bz, Bm + sBb * bz, Cm + sCb * bz,
                          bias, resid ? resid + sRb * bz : nullptr,
                          K, lda, ldb, ldc, scale,
                          blockIdx.y * 128, blockIdx.x * 128);
}

// fused q/k/v projections (z = proj*BATCH + batch)
struct QKVArgs {
    const float* w[3];
    const float* b[3];
    float*       o[3];
};

__global__ __launch_bounds__(256, 2)
void qkv_tc(QKVArgs args, const float* __restrict__ h)
{
    const int pj = blockIdx.z / BATCH;
    const int bz = blockIdx.z % BATCH;
    const size_t sCN = (size_t)CH * NTOK;
    gemm_body<true, true>(args.w[pj], h + sCN * bz, args.o[pj] + sCN * bz,
                          args.b[pj], nullptr,
                          CH, CH, NTOK, NTOK, 1.f,
                          blockIdx.y * 128, blockIdx.x * 128);
}

// ---------------- row softmax over 4096 keys ----------------
__global__ void softmax_kernel()
{
    float* p = g_s + (size_t)blockIdx.x * NTOK;
    const int t = threadIdx.x;
    float vals[16];
    float mx = -1e30f;
    #pragma unroll
    for (int i = 0; i < 16; i++) {
        vals[i] = p[t + (i << 8)];
        mx = fmaxf(mx, vals[i]);
    }
    __shared__ float sh[8];
    #pragma unroll
    for (int o = 16; o; o >>= 1) mx = fmaxf(mx, __shfl_xor_sync(0xFFFFFFFFu, mx, o));
    if (!(t & 31)) sh[t >> 5] = mx;
    __syncthreads();
    if (t < 32) {
        float v = (t < 8) ? sh[t] : -1e30f;
        #pragma unroll
        for (int o = 4; o; o >>= 1) v = fmaxf(v, __shfl_xor_sync(0xFFFFFFFFu, v, o));
        if (!t) sh[0] = v;
    }
    __syncthreads();
    mx = sh[0];
    __syncthreads();

    float sum = 0.f;
    #pragma unroll
    for (int i = 0; i < 16; i++) {
        vals[i] = __expf(vals[i] - mx);
        sum += vals[i];
    }
    #pragma unroll
    for (int o = 16; o; o >>= 1) sum += __shfl_xor_sync(0xFFFFFFFFu, sum, o);
    if (!(t & 31)) sh[t >> 5] = sum;
    __syncthreads();
    if (t < 32) {
        float v = (t < 8) ? sh[t] : 0.f;
        #pragma unroll
        for (int o = 4; o; o >>= 1) v += __shfl_xor_sync(0xFFFFFFFFu, v, o);
        if (!t) sh[0] = v;
    }
    __syncthreads();
    const float inv = 1.f / sh[0];
    #pragma unroll
    for (int i = 0; i < 16; i++) p[t + (i << 8)] = vals[i] * inv;
}

// ---------------- launcher ----------------
extern "C" void kernel_launch(void* const* d_in, const int* in_sizes, int n_in,
                              void* d_out, int out_size)
{
    const float* x     = (const float*)d_in[0];
    const float* gamma = (const float*)d_in[1];
    const float* beta  = (const float*)d_in[2];
    const float* wq    = (const float*)d_in[3];
    const float* bq    = (const float*)d_in[4];
    const float* wk    = (const float*)d_in[5];
    const float* bk    = (const float*)d_in[6];
    const float* wv    = (const float*)d_in[7];
    const float* bv    = (const float*)d_in[8];
    const float* wo    = (const float*)d_in[9];
    const float* bo    = (const float*)d_in[10];
    float* out = (float*)d_out;

    float *h, *q, *k, *v, *ao, *s;
    cudaGetSymbolAddress((void**)&h,  g_h);
    cudaGetSymbolAddress((void**)&q,  g_q);
    cudaGetSymbolAddress((void**)&k,  g_k);
    cudaGetSymbolAddress((void**)&v,  g_v);
    cudaGetSymbolAddress((void**)&ao, g_ao);
    cudaGetSymbolAddress((void**)&s,  g_s);

    const size_t sCN = (size_t)CH * NTOK;
    const size_t sNN = (size_t)NTOK * NTOK;
    const float attn_scale = 0.044194173824159216f;   // 512^-0.5

    // 1) GroupNorm -> g_h
    gn_kernel<<<BATCH * GROUPS, 256>>>(x, gamma, beta);

    // 2) fused Q/K/V projections
    QKVArgs qa;
    qa.w[0] = wq; qa.w[1] = wk; qa.w[2] = wv;
    qa.b[0] = bq; qa.b[1] = bk; qa.b[2] = bv;
    qa.o[0] = q;  qa.o[1] = k;  qa.o[2] = v;
    dim3 gQKV(NTOK / 128, CH / 128, 3 * BATCH);
    qkv_tc<<<gQKV, 256>>>(qa, h);

    // 3) scores = scale * Q^T K
    dim3 gScore(NTOK / 128, NTOK / 128, BATCH);
    gemm_tc<false, true><<<gScore, 256>>>(q, sCN, k, sCN, s, sNN,
                                          (const float*)nullptr,
                                          (const float*)nullptr, 0,
                                          CH, NTOK, NTOK, NTOK, attn_scale);

    // 4) softmax over keys
    softmax_kernel<<<BATCH * NTOK, 256>>>();

    // 5) ao = V * attn^T
    dim3 gAV(NTOK / 128, CH / 128, BATCH);
    gemm_tc<true, false><<<gAV, 256>>>(v, sCN, s, sNN, ao, sCN,
                                       (const float*)nullptr,
                                       (const float*)nullptr, 0,
                                       NTOK, NTOK, NTOK, NTOK, 1.f);

    // 6) out = x + Wo * ao + bo
    dim3 gProj(NTOK / 128, CH / 128, BATCH);
    gemm_tc<true, true><<<gProj, 256>>>(wo, 0, ao, sCN, out, sCN, bo,
                                        x, sCN,
                                        CH, CH, NTOK, NTOK, 1.f);
}

// round 5
// speedup vs baseline: 3.1221x; 1.2074x over previous
#include <cuda_runtime.h>
#include <math.h>

#define BATCH  2
#define CH     512
#define NTOK   4096
#define GROUPS 32
#define CPG    16
#define EPS    1e-6f

#define BK     16
#define KMP    136    // k-major smem pitch (floats): [k][m], m contiguous
#define MKP    20     // row-major smem pitch: [row][k], k contiguous

// ---------------- scratch ----------------
__device__ float g_h [(size_t)BATCH * CH * NTOK];
__device__ float g_q [(size_t)BATCH * CH * NTOK];
__device__ float g_k [(size_t)BATCH * CH * NTOK];
__device__ float g_v [(size_t)BATCH * CH * NTOK];
__device__ float g_ao[(size_t)BATCH * CH * NTOK];
__device__ float g_s [(size_t)BATCH * NTOK * NTOK];
__device__ float g_rsum[(size_t)BATCH * NTOK];

// ---------------- GroupNorm ----------------
__global__ void gn_kernel(const float* __restrict__ x,
                          const float* __restrict__ gamma,
                          const float* __restrict__ beta)
{
    const int bg = blockIdx.x;
    const int b = bg / GROUPS, g = bg % GROUPS;
    const size_t base = ((size_t)b * CH + (size_t)g * CPG) * NTOK;
    const float* xp = x + base;
    float* hp = g_h + base;
    const int M = CPG * NTOK;

    float s = 0.f, s2 = 0.f;
    for (int i = threadIdx.x * 4; i < M; i += blockDim.x * 4) {
        float4 v = *(const float4*)&xp[i];
        s  += v.x + v.y + v.z + v.w;
        s2 += v.x*v.x + v.y*v.y + v.z*v.z + v.w*v.w;
    }
    __shared__ float shs[8], shs2[8], shbc[2];
    #pragma unroll
    for (int o = 16; o; o >>= 1) {
        s  += __shfl_xor_sync(0xFFFFFFFFu, s,  o);
        s2 += __shfl_xor_sync(0xFFFFFFFFu, s2, o);
    }
    const int wid = threadIdx.x >> 5, lane = threadIdx.x & 31;
    if (!lane) { shs[wid] = s; shs2[wid] = s2; }
    __syncthreads();
    if (threadIdx.x == 0) {
        float ts = 0.f, ts2 = 0.f;
        #pragma unroll
        for (int i = 0; i < 8; i++) { ts += shs[i]; ts2 += shs2[i]; }
        const float mean = ts / (float)M;
        const float var  = ts2 / (float)M - mean * mean;
        shbc[0] = mean;
        shbc[1] = rsqrtf(var + EPS);
    }
    __syncthreads();
    const float mean = shbc[0], rstd = shbc[1];
    for (int i = threadIdx.x * 4; i < M; i += blockDim.x * 4) {
        const int c = g * CPG + (i >> 12);
        const float ga = gamma[c] * rstd;
        const float be = beta[c] - mean * ga;
        float4 v = *(const float4*)&xp[i];
        float4 o;
        o.x = v.x * ga + be; o.y = v.y * ga + be;
        o.z = v.z * ga + be; o.w = v.w * ga + be;
        *(float4*)&hp[i] = o;
    }
}

__global__ void zero_kernel(float* p, int n)
{
    int i = blockIdx.x * blockDim.x + threadIdx.x;
    if (i < n) p[i] = 0.f;
}

// ---------------- cp.async staging ----------------
__device__ __forceinline__ void cpa16(float* dst, const float* src)
{
    unsigned s = (unsigned)__cvta_generic_to_shared(dst);
    asm volatile("cp.async.cg.shared.global [%0], [%1], 16;" :: "r"(s), "l"(src));
}

// KM tile: 16 k-rows x 128 cols -> smem[k*KMP + m]
__device__ __forceinline__ void stage_km(float* dst, const float* src, int ld, int tid)
{
    #pragma unroll
    for (int c = tid; c < 512; c += 256) {
        const int k = c >> 5, m4 = (c & 31) << 2;
        cpa16(dst + k * KMP + m4, src + (size_t)k * ld + m4);
    }
}
// MK tile: 128 rows x 16 k -> smem[row*MKP + k]
__device__ __forceinline__ void stage_mk(float* dst, const float* src, int ld, int tid)
{
    #pragma unroll
    for (int c = tid; c < 512; c += 256) {
        const int row = c >> 2, k4 = (c & 3) << 2;
        cpa16(dst + row * MKP + k4, src + (size_t)row * ld + k4);
    }
}

__device__ __forceinline__ unsigned ubits(float f) { return __float_as_uint(f); }

// ---------------- tf32 tensor-core GEMM core ----------------
// C[m,n] = scale * sum_k A(m,k)*B(k,n) (+bias[m]) (+resid) [exp + rowsum] [/ colscale[n]]
// 2-stage cp.async double buffer; smem sized per-layout to fit 48KB static limit.
template<bool A_KC, bool B_NC, bool DO_EXP, bool COLSCALE>
__device__ __forceinline__
void gemm_body(const float* __restrict__ A,
               const float* __restrict__ Bm,
               float* __restrict__ Cm,
               const float* __restrict__ bias,
               const float* __restrict__ resid,
               float* __restrict__ rsum,
               int K, int lda, int ldb, int ldc, float scale,
               int m0, int n0)
{
    constexpr int SAF = A_KC ? 128 * MKP : 16 * KMP;
    constexpr int SBF = B_NC ? 16 * KMP : 128 * MKP;
    __shared__ float SA[2][SAF];
    __shared__ float SB[2][SBF];

    const int tid = threadIdx.x;
    const int warp = tid >> 5, lane = tid & 31;
    const int wm = (warp >> 2) * 64;
    const int wn = (warp & 3) * 32;
    const int grp = lane >> 2;
    const int tig = lane & 3;

    const float* Ab = A_KC ? (A + (size_t)m0 * lda) : (A + m0);
    const float* Bb = B_NC ? (Bm + n0) : (Bm + (size_t)n0 * ldb);

    const int nslab = K / BK;

    // prologue: issue slab 0
    if (A_KC) stage_mk(SA[0], Ab, lda, tid); else stage_km(SA[0], Ab, lda, tid);
    if (B_NC) stage_km(SB[0], Bb, ldb, tid); else stage_mk(SB[0], Bb, ldb, tid);
    asm volatile("cp.async.commit_group;");

    float acc[4][4][4];
    #pragma unroll
    for (int a = 0; a < 4; a++)
        #pragma unroll
        for (int b = 0; b < 4; b++)
            #pragma unroll
            for (int c = 0; c < 4; c++) acc[a][b][c] = 0.f;

    int buf = 0;
    for (int s = 0; s < nslab; s++) {
        asm volatile("cp.async.wait_group 0;");
        __syncthreads();

        if (s + 1 < nslab) {
            const size_t ko = (size_t)(s + 1) * BK;
            const float* As = A_KC ? (Ab + ko) : (Ab + ko * lda);
            const float* Bs = B_NC ? (Bb + ko * ldb) : (Bb + ko);
            const int nb = buf ^ 1;
            if (A_KC) stage_mk(SA[nb], As, lda, tid); else stage_km(SA[nb], As, lda, tid);
            if (B_NC) stage_km(SB[nb], Bs, ldb, tid); else stage_mk(SB[nb], Bs, ldb, tid);
            asm volatile("cp.async.commit_group;");
        }

        const float* sa = SA[buf];
        const float* sb = SB[buf];
        #pragma unroll
        for (int kc = 0; kc < BK; kc += 8) {
            const int ka = kc + tig, kb = kc + tig + 4;
            unsigned af[4][4], bf[4][2];
            #pragma unroll
            for (int mi = 0; mi < 4; mi++) {
                const int m = wm + mi * 16 + grp;
                if (A_KC) {
                    af[mi][0] = ubits(sa[m * MKP + ka]);
                    af[mi][1] = ubits(sa[(m + 8) * MKP + ka]);
                    af[mi][2] = ubits(sa[m * MKP + kb]);
                    af[mi][3] = ubits(sa[(m + 8) * MKP + kb]);
                } else {
                    af[mi][0] = ubits(sa[ka * KMP + m]);
                    af[mi][1] = ubits(sa[ka * KMP + m + 8]);
                    af[mi][2] = ubits(sa[kb * KMP + m]);
                    af[mi][3] = ubits(sa[kb * KMP + m + 8]);
                }
            }
            #pragma unroll
            for (int nj = 0; nj < 4; nj++) {
                const int n = wn + nj * 8 + grp;
                if (B_NC) {
                    bf[nj][0] = ubits(sb[ka * KMP + n]);
                    bf[nj][1] = ubits(sb[kb * KMP + n]);
                } else {
                    bf[nj][0] = ubits(sb[n * MKP + ka]);
                    bf[nj][1] = ubits(sb[n * MKP + kb]);
                }
            }
            #pragma unroll
            for (int mi = 0; mi < 4; mi++)
                #pragma unroll
                for (int nj = 0; nj < 4; nj++) {
                    asm volatile(
                        "mma.sync.aligned.m16n8k8.row.col.f32.tf32.tf32.f32 "
                        "{%0,%1,%2,%3}, {%4,%5,%6,%7}, {%8,%9}, {%0,%1,%2,%3};"
                        : "+f"(acc[mi][nj][0]), "+f"(acc[mi][nj][1]),
                          "+f"(acc[mi][nj][2]), "+f"(acc[mi][nj][3])
                        : "r"(af[mi][0]), "r"(af[mi][1]),
                          "r"(af[mi][2]), "r"(af[mi][3]),
                          "r"(bf[nj][0]), "r"(bf[nj][1]));
                }
        }
        buf ^= 1;
    }

    // ---- epilogue
    float inv[4][2];
    if (COLSCALE) {
        #pragma unroll
        for (int nj = 0; nj < 4; nj++) {
            const int n = n0 + wn + nj * 8 + (tig << 1);
            inv[nj][0] = 1.f / rsum[n];
            inv[nj][1] = 1.f / rsum[n + 1];
        }
    }
    float rsA[4], rsB[4];
    #pragma unroll
    for (int mi = 0; mi < 4; mi++) { rsA[mi] = 0.f; rsB[mi] = 0.f; }

    #pragma unroll
    for (int mi = 0; mi < 4; mi++) {
        const int mA = m0 + wm + mi * 16 + grp;
        const int mB = mA + 8;
        const float bvA = bias ? bias[mA] : 0.f;
        const float bvB = bias ? bias[mB] : 0.f;
        #pragma unroll
        for (int nj = 0; nj < 4; nj++) {
            const int n = n0 + wn + nj * 8 + (tig << 1);
            float2 o0, o1;
            o0.x = acc[mi][nj][0] * scale + bvA;
            o0.y = acc[mi][nj][1] * scale + bvA;
            o1.x = acc[mi][nj][2] * scale + bvB;
            o1.y = acc[mi][nj][3] * scale + bvB;
            if (DO_EXP) {
                o0.x = __expf(o0.x); o0.y = __expf(o0.y);
                o1.x = __expf(o1.x); o1.y = __expf(o1.y);
                rsA[mi] += o0.x + o0.y;
                rsB[mi] += o1.x + o1.y;
            }
            if (COLSCALE) {
                o0.x *= inv[nj][0]; o0.y *= inv[nj][1];
                o1.x *= inv[nj][0]; o1.y *= inv[nj][1];
            }
            if (resid) {
                float2 r0 = *(const float2*)&resid[(size_t)mA * ldc + n];
                float2 r1 = *(const float2*)&resid[(size_t)mB * ldc + n];
                o0.x += r0.x; o0.y += r0.y;
                o1.x += r1.x; o1.y += r1.y;
            }
            *(float2*)&Cm[(size_t)mA * ldc + n] = o0;
            *(float2*)&Cm[(size_t)mB * ldc + n] = o1;
        }
    }
    if (DO_EXP) {
        #pragma unroll
        for (int mi = 0; mi < 4; mi++) {
            float a = rsA[mi], b = rsB[mi];
            a += __shfl_xor_sync(0xFFFFFFFFu, a, 1);
            a += __shfl_xor_sync(0xFFFFFFFFu, a, 2);
            b += __shfl_xor_sync(0xFFFFFFFFu, b, 1);
            b += __shfl_xor_sync(0xFFFFFFFFu, b, 2);
            if (tig == 0) {
                const int mA = m0 + wm + mi * 16 + grp;
                atomicAdd(&rsum[mA], a);
                atomicAdd(&rsum[mA + 8], b);
            }
        }
    }
}

template<bool A_KC, bool B_NC, bool DO_EXP, bool COLSCALE>
__global__ __launch_bounds__(256, 2)
void gemm_tc(const float* __restrict__ A,  size_t sAb,
             const float* __restrict__ Bm, size_t sBb,
             float* __restrict__ Cm,       size_t sCb,
             const float* __restrict__ bias,
             const float* __restrict__ resid, size_t sRb,
             float* rsum,
             int K, int lda, int ldb, int ldc, float scale)
{
    const int bz = blockIdx.z;
    gemm_body<A_KC, B_NC, DO_EXP, COLSCALE>(
        A + sAb * bz, Bm + sBb * bz, Cm + sCb * bz,
        bias, resid ? resid + sRb * bz : nullptr,
        rsum ? rsum + (size_t)NTOK * bz : nullptr,
        K, lda, ldb, ldc, scale,
        blockIdx.y * 128, blockIdx.x * 128);
}

struct QKVArgs {
    const float* w[3];
    const float* b[3];
    float*       o[3];
};

__global__ __launch_bounds__(256, 2)
void qkv_tc(QKVArgs args, const float* __restrict__ h)
{
    const int pj = blockIdx.z / BATCH;
    const int bz = blockIdx.z % BATCH;
    const size_t sCN = (size_t)CH * NTOK;
    gemm_body<true, true, false, false>(
        args.w[pj], h + sCN * bz, args.o[pj] + sCN * bz,
        args.b[pj], nullptr, nullptr,
        CH, CH, NTOK, NTOK, 1.f,
        blockIdx.y * 128, blockIdx.x * 128);
}

// ---------------- launcher ----------------
extern "C" void kernel_launch(void* const* d_in, const int* in_sizes, int n_in,
                              void* d_out, int out_size)
{
    const float* x     = (const float*)d_in[0];
    const float* gamma = (const float*)d_in[1];
    const float* beta  = (const float*)d_in[2];
    const float* wq    = (const float*)d_in[3];
    const float* bq    = (const float*)d_in[4];
    const float* wk    = (const float*)d_in[5];
    const float* bk    = (const float*)d_in[6];
    const float* wv    = (const float*)d_in[7];
    const float* bv    = (const float*)d_in[8];
    const float* wo    = (const float*)d_in[9];
    const float* bo    = (const float*)d_in[10];
    float* out = (float*)d_out;

    float *h, *q, *k, *v, *ao, *s, *rsum;
    cudaGetSymbolAddress((void**)&h,    g_h);
    cudaGetSymbolAddress((void**)&q,    g_q);
    cudaGetSymbolAddress((void**)&k,    g_k);
    cudaGetSymbolAddress((void**)&v,    g_v);
    cudaGetSymbolAddress((void**)&ao,   g_ao);
    cudaGetSymbolAddress((void**)&s,    g_s);
    cudaGetSymbolAddress((void**)&rsum, g_rsum);

    const size_t sCN = (size_t)CH * NTOK;
    const size_t sNN = (size_t)NTOK * NTOK;
    const float attn_scale = 0.044194173824159216f;   // 512^-0.5

    // 1) GroupNorm -> g_h
    gn_kernel<<<BATCH * GROUPS, 256>>>(x, gamma, beta);

    // 2) fused Q/K/V projections
    QKVArgs qa;
    qa.w[0] = wq; qa.w[1] = wk; qa.w[2] = wv;
    qa.b[0] = bq; qa.b[1] = bk; qa.b[2] = bv;
    qa.o[0] = q;  qa.o[1] = k;  qa.o[2] = v;
    dim3 gQKV(NTOK / 128, CH / 128, 3 * BATCH);
    qkv_tc<<<gQKV, 256>>>(qa, h);

    // 3) zero rowsums
    zero_kernel<<<(BATCH * NTOK + 255) / 256, 256>>>(rsum, BATCH * NTOK);

    // 4) exp-scores = exp(scale * Q^T K), accumulate rowsums
    dim3 gScore(NTOK / 128, NTOK / 128, BATCH);
    gemm_tc<false, true, true, false><<<gScore, 256>>>(
        q, sCN, k, sCN, s, sNN,
        (const float*)nullptr, (const float*)nullptr, 0, rsum,
        CH, NTOK, NTOK, NTOK, attn_scale);

    // 5) ao = (V * expS^T) / rowsum[n]
    dim3 gAV(NTOK / 128, CH / 128, BATCH);
    gemm_tc<true, false, false, true><<<gAV, 256>>>(
        v, sCN, s, sNN, ao, sCN,
        (const float*)nullptr, (const float*)nullptr, 0, rsum,
        NTOK, NTOK, NTOK, NTOK, 1.f);

    // 6) out = x + Wo * ao + bo
    dim3 gProj(NTOK / 128, CH / 128, BATCH);
    gemm_tc<true, true, false, false><<<gProj, 256>>>(
        wo, 0, ao, sCN, out, sCN, bo,
        x, sCN, (float*)nullptr,
        CH, CH, NTOK, NTOK, 1.f);
}